// round 7
// baseline (speedup 1.0000x reference)
#include <cuda_runtime.h>
#include <climits>

// Problem constants (fixed by reference setup_inputs)
#define BB     4096
#define HH     64
#define WW     64
#define HWC    4096            // H*W
#define LATENT 128
#define NT     256             // threads per block
#define SPLIT  4               // CTAs per row
#define CPP    (HWC / SPLIT)   // 1024 cells per part
#define CPT    (CPP / NT)      // 4 cells per thread

// Static scratch (no allocations allowed). g_cnt is zero-initialized at module
// load and self-resets each launch via atomicInc's wrap (0,1,2,3 -> 0).
__device__ unsigned g_cnt[BB];
__device__ int      g_food[BB][SPLIT];
__device__ int      g_opp[BB][SPLIT];
__device__ unsigned g_mask[BB][HWC / 32];   // 128 words per row

__global__ __launch_bounds__(NT)
void oracle_kernel(const float4* __restrict__ x,     // (B, HW) cells of 4 floats
                   const float*  __restrict__ proj,  // (128,)
                   float* __restrict__ out)          // (2, B, 128)
{
    const int cta  = blockIdx.x;
    const int b    = cta >> 2;          // row
    const int part = cta & 3;           // quarter of the row
    const int t    = threadIdx.x;
    const int lane = t & 31;
    const int warp = t >> 5;

    __shared__ int s_foodCnt;
    __shared__ int s_oppMin;
    __shared__ int s_minKey;
    __shared__ int s_flag;
    __shared__ unsigned s_mask[HWC / 32];
    __shared__ int s_nf, s_oi;

    if (t == 0) { s_foodCnt = 0; s_oppMin = INT_MAX; s_minKey = INT_MAX; }
    __syncthreads();

    // ---- Phase 1: stream this CTA's 16KB quarter-row
    const float4* xb = x + (size_t)b * HWC + part * CPP;

    float4 v[CPT];
    #pragma unroll
    for (int i = 0; i < CPT; i++)
        v[i] = __ldcs(&xb[i * NT + t]);       // read-once streaming, MLP=4

    int lf = 0;
    int lo = INT_MAX;
    #pragma unroll
    for (int i = 0; i < CPT; i++) {
        const int cellLocal = i * NT + t;                 // within part
        const bool food = (v[i].y == 1.0f);               // channel 1
        const bool opp  = (v[i].w == 1.0f);               // channel 3
        const unsigned bal = __ballot_sync(0xffffffffu, food);
        if (lane == 0)
            g_mask[b][part * (CPP / 32) + i * (NT / 32) + warp] = bal;
        lf += (int)food;
        if (opp) lo = min(lo, part * CPP + cellLocal);
    }
    #pragma unroll
    for (int o = 16; o; o >>= 1) {
        lf += __shfl_down_sync(0xffffffffu, lf, o);
        lo  = min(lo, __shfl_down_sync(0xffffffffu, lo, o));
    }
    if (lane == 0) {
        atomicAdd(&s_foodCnt, lf);
        atomicMin(&s_oppMin, lo);
    }
    // Make this thread's global stores (mask words) gpu-visible before the
    // arrival atomic (threadFenceReduction pattern).
    __threadfence();
    __syncthreads();

    if (t == 0) {
        g_food[b][part] = s_foodCnt;
        g_opp[b][part]  = s_oppMin;
        __threadfence();
        const unsigned old = atomicInc(&g_cnt[b], SPLIT - 1);  // wraps to 0
        s_flag = (old == SPLIT - 1);
        // re-init for finalize phase
        s_minKey = INT_MAX;
    }
    __syncthreads();
    if (!s_flag) return;

    // ---- Phase 2 (last-arriving CTA only): finalize the row
    __threadfence();   // acquire side: order scratch reads after the atomic

    if (t < HWC / 32) s_mask[t] = __ldcg(&g_mask[b][t]);
    if (t == 0) {
        int nf = 0, oi = INT_MAX;
        #pragma unroll
        for (int p = 0; p < SPLIT; p++) {
            nf += __ldcg(&g_food[b][p]);
            oi  = min(oi, __ldcg(&g_opp[b][p]));
        }
        s_nf = nf;
        s_oi = (oi == INT_MAX) ? 0 : oi;   // jnp.argmax over all-false -> 0
    }
    __syncthreads();

    const int orow = s_oi >> 6;
    const int ocol = s_oi & 63;

    // argmin of integer d2 over food cells, row-major tie-break.
    // key = (d2 << 12) | cell  (d2 <= 7938, cell < 4096 -> key < 2^31).
    // sqrtf in the reference is a monotone map of integer d2 with no rounding
    // collisions in this range, so integer ordering is exact.
    int key = INT_MAX;
    #pragma unroll
    for (int i = 0; i < HWC / NT; i++) {
        const int cell = i * NT + t;
        if ((s_mask[cell >> 5] >> (cell & 31)) & 1u) {
            const int dr = (cell >> 6) - orow;
            const int dc = (cell & 63) - ocol;
            const int d2 = dr * dr + dc * dc;
            key = min(key, (d2 << 12) | cell);
        }
    }
    #pragma unroll
    for (int o = 16; o; o >>= 1)
        key = min(key, __shfl_down_sync(0xffffffffu, key, o));
    if (lane == 0) atomicMin(&s_minKey, key);
    __syncthreads();

    // ---- Branch logic
    float s = 0.0f;
    const int nf = s_nf;
    if (nf >= 1) {
        const bool oppAtStart = (orow == 3) && (ocol == 6);
        if (nf == 1 || !oppAtStart) {
            const int targetRow = (s_minKey & 4095) >> 6;
            s = (targetRow < (HH / 2)) ? 1.0f : -1.0f;
        }
    }

    // ---- Write g (threads 0..127) and the zero half (threads 128..255)
    if (t < LATENT) {
        out[(size_t)b * LATENT + t] = s * proj[t];
    } else {
        out[(size_t)BB * LATENT + (size_t)b * LATENT + (t - LATENT)] = 0.0f;
    }
}

extern "C" void kernel_launch(void* const* d_in, const int* in_sizes, int n_in,
                              void* d_out, int out_size)
{
    const float4* x    = (const float4*)d_in[0];   // (4096,64,64,4) fp32
    const float*  proj = (const float*)d_in[1];    // (128,) fp32
    float*        out  = (float*)d_out;            // 2*4096*128 fp32

    oracle_kernel<<<BB * SPLIT, NT>>>(x, proj, out);
}

// round 8
// speedup vs baseline: 1.3834x; 1.3834x over previous
#include <cuda_runtime.h>
#include <climits>

// Problem constants (fixed by reference setup_inputs)
#define BB   4096
#define HH   64
#define WW   64
#define HWC  4096          // H*W
#define LATENT 128
#define NT   256           // threads per block
#define CPT  (HWC / NT)    // 16 cells per thread

__global__ __launch_bounds__(NT)
void oracle_kernel(const float4* __restrict__ x,     // (B, HW) cells of 4 floats
                   const float*  __restrict__ proj,  // (128,)
                   float* __restrict__ out)          // (2, B, 128)
{
    const int b    = blockIdx.x;
    const int t    = threadIdx.x;
    const int lane = t & 31;

    __shared__ int s_oppMin;                  // min flat index of opponent
    __shared__ int s_foodCnt;
    __shared__ int s_minKey;                  // (d2 << 12) | cell

    if (t == 0) { s_oppMin = INT_MAX; s_foodCnt = 0; s_minKey = INT_MAX; }

    // Zero half of the output depends on nothing: emit it up front so these
    // stores overlap the input stream instead of extending the CTA tail.
    if (t >= LATENT) {
        out[(size_t)BB * LATENT + (size_t)b * LATENT + (t - LATENT)] = 0.0f;
    }
    __syncthreads();

    const float4* xb = x + (size_t)b * HWC;

    // ---- Pass 1: stream the 64KB row. Each thread keeps its own 16 food
    // flags in a register bitmask; loads batched 4-wide (MLP >= 4).
    unsigned foodBits = 0;
    int localFood = 0;
    int localOpp  = INT_MAX;
    #pragma unroll
    for (int g = 0; g < CPT / 4; g++) {
        float4 v[4];
        #pragma unroll
        for (int j = 0; j < 4; j++)
            v[j] = __ldcs(&xb[(g * 4 + j) * NT + t]);   // streaming: read-once
        #pragma unroll
        for (int j = 0; j < 4; j++) {
            const int i    = g * 4 + j;
            const int cell = i * NT + t;
            const bool food = (v[j].y == 1.0f);         // channel 1
            const bool opp  = (v[j].w == 1.0f);         // channel 3
            foodBits |= ((unsigned)food) << i;
            localFood += (int)food;
            if (opp) localOpp = min(localOpp, cell);
        }
    }
    #pragma unroll
    for (int o = 16; o; o >>= 1) {
        localFood += __shfl_down_sync(0xffffffffu, localFood, o);
        localOpp   = min(localOpp, __shfl_down_sync(0xffffffffu, localOpp, o));
    }
    if (lane == 0) {
        atomicAdd(&s_foodCnt, localFood);
        atomicMin(&s_oppMin, localOpp);
    }
    __syncthreads();

    // jnp.argmax over all-false mask -> index 0
    const int oppIdx = (s_oppMin == INT_MAX) ? 0 : s_oppMin;
    const int orow = oppIdx >> 6;
    const int ocol = oppIdx & 63;

    // ---- Pass 2: argmin of integer d2 over this thread's food cells,
    // row-major tie-break. key = (d2 << 12) | cell  (d2 <= 7938, cell < 4096).
    // sqrtf in the reference is a monotone map of integer d2 with no rounding
    // collisions in this range, so integer ordering is exact.
    int localKey = INT_MAX;
    unsigned fb = foodBits;
    while (fb) {
        const int i = __ffs(fb) - 1;
        fb &= fb - 1;
        const int cell = i * NT + t;
        const int dr = (cell >> 6) - orow;
        const int dc = (cell & 63) - ocol;
        const int d2 = dr * dr + dc * dc;
        localKey = min(localKey, (d2 << 12) | cell);
    }
    #pragma unroll
    for (int o = 16; o; o >>= 1)
        localKey = min(localKey, __shfl_down_sync(0xffffffffu, localKey, o));
    if (lane == 0) atomicMin(&s_minKey, localKey);
    __syncthreads();

    // ---- Branch logic + g write (threads 0..127 only)
    if (t < LATENT) {
        float s = 0.0f;
        const int nf = s_foodCnt;
        if (nf >= 1) {
            const bool oppAtStart = (orow == 3) && (ocol == 6);
            if (nf == 1 || !oppAtStart) {
                const int targetRow = (s_minKey & 4095) >> 6;
                s = (targetRow < (HH / 2)) ? 1.0f : -1.0f;
            }
        }
        out[(size_t)b * LATENT + t] = s * __ldg(&proj[t]);
    }
}

extern "C" void kernel_launch(void* const* d_in, const int* in_sizes, int n_in,
                              void* d_out, int out_size)
{
    const float4* x    = (const float4*)d_in[0];   // (4096,64,64,4) fp32
    const float*  proj = (const float*)d_in[1];    // (128,) fp32
    float*        out  = (float*)d_out;            // 2*4096*128 fp32

    oracle_kernel<<<BB, NT>>>(x, proj, out);
}